// round 2
// baseline (speedup 1.0000x reference)
#include <cuda_runtime.h>

#define NU 100000
#define NI 50000
#define NN 150000            // NU + NI
#define NE 3000000
#define DIM 128
#define D4  32               // DIM / 4
#define NLAYERS 3

#define SCAN_B 1024
#define SCAN_NB 147          // ceil(NN / 1024)

// ---- device scratch (allocation-free requirement) ----
__device__ float4 g_emb[2][(size_t)NN * D4];   // ping-pong layer buffers (16B aligned)
__device__ int    g_deg[NN];
__device__ float  g_inv[NN];
__device__ int    g_off[NN + 1];
__device__ int    g_cur[NN];
__device__ int    g_csr[NE];
__device__ int    g_part[SCAN_NB];
__device__ int    g_is64;

// ---- 0a) detect edge_index element width: int64 stores high word = 0 ----
__global__ void k_detect(const int* __restrict__ ei32) {
    __shared__ int s_or[256];
    int acc = 0;
    for (int i = threadIdx.x; i < 4096; i += 256) acc |= ei32[2 * i + 1];
    s_or[threadIdx.x] = acc;
    __syncthreads();
    for (int d = 128; d > 0; d >>= 1) {
        if (threadIdx.x < d) s_or[threadIdx.x] |= s_or[threadIdx.x + d];
        __syncthreads();
    }
    if (threadIdx.x == 0) g_is64 = (s_or[0] == 0) ? 1 : 0;
}

__device__ __forceinline__ void load_edge(const void* ei, int is64, int e,
                                          int& src, int& dst) {
    if (is64) {
        src = (int)((const long long*)ei)[e];
        dst = (int)((const long long*)ei)[NE + e];
    } else {
        src = ((const int*)ei)[e];
        dst = ((const int*)ei)[NE + e];
    }
}

// ---- 0b) zero degree array ----
__global__ void k_zero_deg() {
    int i = blockIdx.x * blockDim.x + threadIdx.x;
    if (i < NN) g_deg[i] = 0;
}

// ---- 1) init ego embeddings: emb[0] = cat(user, item); total(d_out) = same ----
__global__ void k_init_emb(const float4* __restrict__ u4,
                           const float4* __restrict__ i4,
                           float4* __restrict__ out4) {
    const int n4 = NN * D4;
    const int u_n4 = NU * D4;
    for (int i = blockIdx.x * blockDim.x + threadIdx.x; i < n4;
         i += gridDim.x * blockDim.x) {
        float4 v = (i < u_n4) ? u4[i] : i4[i - u_n4];
        g_emb[0][i] = v;
        out4[i]     = v;
    }
}

// ---- 2) degree histogram over dst ----
__global__ void k_hist(const void* __restrict__ ei) {
    const int is64 = g_is64;
    for (int e = blockIdx.x * blockDim.x + threadIdx.x; e < NE;
         e += gridDim.x * blockDim.x) {
        int src, dst;
        load_edge(ei, is64, e, src, dst);
        if ((unsigned)dst < NN) atomicAdd(&g_deg[dst], 1);
    }
}

// ---- 3a) block-local exclusive scan of deg -> g_off, block sums -> g_part ----
__global__ void k_scan1() {
    __shared__ int sh[SCAN_B];
    int gid = blockIdx.x * SCAN_B + threadIdx.x;
    int v = (gid < NN) ? g_deg[gid] : 0;
    sh[threadIdx.x] = v;
    __syncthreads();
    for (int d = 1; d < SCAN_B; d <<= 1) {
        int t = (threadIdx.x >= d) ? sh[threadIdx.x - d] : 0;
        __syncthreads();
        sh[threadIdx.x] += t;
        __syncthreads();
    }
    int incl = sh[threadIdx.x];
    if (gid < NN) g_off[gid] = incl - v;          // exclusive
    if (threadIdx.x == SCAN_B - 1) g_part[blockIdx.x] = incl;
}

// ---- 3b) single-block exclusive scan of block sums ----
__global__ void k_scan2() {
    __shared__ int sh[256];
    int tid = threadIdx.x;
    int v = (tid < SCAN_NB) ? g_part[tid] : 0;
    sh[tid] = v;
    __syncthreads();
    for (int d = 1; d < 256; d <<= 1) {
        int t = (tid >= d) ? sh[tid - d] : 0;
        __syncthreads();
        sh[tid] += t;
        __syncthreads();
    }
    if (tid < SCAN_NB) g_part[tid] = sh[tid] - v; // exclusive
}

// ---- 3c) add block offsets, init cursor, compute inv_deg ----
__global__ void k_scan3() {
    int gid = blockIdx.x * SCAN_B + threadIdx.x;
    if (gid < NN) {
        int o = g_off[gid] + g_part[blockIdx.x];
        g_off[gid] = o;
        g_cur[gid] = o;
        int d = g_deg[gid];
        g_inv[gid] = (d > 0) ? (1.0f / (float)d) : 0.0f;
    }
    if (gid == 0) g_off[NN] = NE;
}

// ---- 4) scatter src indices into CSR slots ----
__global__ void k_scatter(const void* __restrict__ ei) {
    const int is64 = g_is64;
    for (int e = blockIdx.x * blockDim.x + threadIdx.x; e < NE;
         e += gridDim.x * blockDim.x) {
        int src, dst;
        load_edge(ei, is64, e, src, dst);
        if ((unsigned)dst < NN && (unsigned)src < NN) {
            int pos = atomicAdd(&g_cur[dst], 1);
            g_csr[pos] = src;
        }
    }
}

// ---- 5) one propagation layer: out[n] = inv[n] * sum_{s in N(n)} in[s];
//         total += out.  One warp per node, lane handles 4 dims (float4). ----
__global__ void k_layer(int in_idx, float4* __restrict__ total) {
    const float4* __restrict__ in4 = g_emb[in_idx];
    float4* __restrict__ out4      = g_emb[in_idx ^ 1];

    int warp = (blockIdx.x * blockDim.x + threadIdx.x) >> 5;
    if (warp >= NN) return;
    int lane = threadIdx.x & 31;

    int beg = g_off[warp];
    int end = g_off[warp + 1];

    float sx = 0.f, sy = 0.f, sz = 0.f, sw = 0.f;
    int e = beg;
    for (; e + 3 < end; e += 4) {
        int s0 = g_csr[e];
        int s1 = g_csr[e + 1];
        int s2 = g_csr[e + 2];
        int s3 = g_csr[e + 3];
        float4 v0 = in4[(size_t)s0 * D4 + lane];
        float4 v1 = in4[(size_t)s1 * D4 + lane];
        float4 v2 = in4[(size_t)s2 * D4 + lane];
        float4 v3 = in4[(size_t)s3 * D4 + lane];
        sx += v0.x + v1.x + v2.x + v3.x;
        sy += v0.y + v1.y + v2.y + v3.y;
        sz += v0.z + v1.z + v2.z + v3.z;
        sw += v0.w + v1.w + v2.w + v3.w;
    }
    for (; e < end; ++e) {
        int s = g_csr[e];
        float4 v = in4[(size_t)s * D4 + lane];
        sx += v.x; sy += v.y; sz += v.z; sw += v.w;
    }

    float idg = g_inv[warp];
    float4 r;
    r.x = sx * idg; r.y = sy * idg; r.z = sz * idg; r.w = sw * idg;

    size_t oi = (size_t)warp * D4 + lane;
    out4[oi] = r;

    float4 t = total[oi];
    t.x += r.x; t.y += r.y; t.z += r.z; t.w += r.w;
    total[oi] = t;
}

// ---- 6) final scale: total /= (NLAYERS + 1) ----
__global__ void k_scale(float4* __restrict__ out4) {
    const int n4 = NN * D4;
    const float s = 1.0f / (float)(NLAYERS + 1);
    for (int i = blockIdx.x * blockDim.x + threadIdx.x; i < n4;
         i += gridDim.x * blockDim.x) {
        float4 v = out4[i];
        v.x *= s; v.y *= s; v.z *= s; v.w *= s;
        out4[i] = v;
    }
}

extern "C" void kernel_launch(void* const* d_in, const int* in_sizes, int n_in,
                              void* d_out, int out_size) {
    const float4* u4  = (const float4*)d_in[0];
    const float4* i4  = (const float4*)d_in[1];
    const void*   ei  = d_in[2];
    float4*       out = (float4*)d_out;

    // dtype detection + CSR build
    k_detect<<<1, 256>>>((const int*)ei);
    k_zero_deg<<<(NN + 255) / 256, 256>>>();
    k_init_emb<<<4096, 256>>>(u4, i4, out);
    k_hist<<<2048, 256>>>(ei);
    k_scan1<<<SCAN_NB, SCAN_B>>>();
    k_scan2<<<1, 256>>>();
    k_scan3<<<SCAN_NB, SCAN_B>>>();
    k_scatter<<<2048, 256>>>(ei);

    // 3 propagation layers (warp per node), total accumulated into d_out
    const int layer_blocks = (NN * 32 + 255) / 256;
    k_layer<<<layer_blocks, 256>>>(0, out);  // emb0 -> emb1
    k_layer<<<layer_blocks, 256>>>(1, out);  // emb1 -> emb0
    k_layer<<<layer_blocks, 256>>>(0, out);  // emb0 -> emb1

    k_scale<<<4096, 256>>>(out);
}

// round 3
// speedup vs baseline: 1.4163x; 1.4163x over previous
#include <cuda_runtime.h>
#include <cuda_fp16.h>

#define NU 100000
#define NI 50000
#define NN 150000            // NU + NI
#define NE 3000000
#define DIM 128
#define D4  32               // DIM / 4 (float4 chunks)
#define D8  32               // DIM / 4 halves per uint2 chunk (same count)

#define SCAN_B 1024
#define SCAN_NB 147          // ceil(NN / 1024)

// ---- device scratch (allocation-free requirement) ----
// 4 fp16 embedding buffers: [0]=x, [1]=a1, [2]=a2, [3]=a3. Each row = 32 uint2 (128 halves).
__device__ uint2 g_h[4][(size_t)NN * 32];
__device__ int    g_deg[NN];
__device__ float  g_inv[NN];
__device__ int    g_off[NN + 1];
__device__ int    g_cur[NN];
__device__ int    g_csr[NE];
__device__ int    g_part[SCAN_NB];
__device__ int    g_is64;

// ---- 0a) detect edge_index element width: int64 stores high word = 0 ----
__global__ void k_detect(const int* __restrict__ ei32) {
    __shared__ int s_or[256];
    int acc = 0;
    for (int i = threadIdx.x; i < 4096; i += 256) acc |= ei32[2 * i + 1];
    s_or[threadIdx.x] = acc;
    __syncthreads();
    for (int d = 128; d > 0; d >>= 1) {
        if (threadIdx.x < d) s_or[threadIdx.x] |= s_or[threadIdx.x + d];
        __syncthreads();
    }
    if (threadIdx.x == 0) g_is64 = (s_or[0] == 0) ? 1 : 0;
}

__device__ __forceinline__ void load_edge(const void* ei, int is64, int e,
                                          int& src, int& dst) {
    if (is64) {
        src = (int)((const long long*)ei)[e];
        dst = (int)((const long long*)ei)[NE + e];
    } else {
        src = ((const int*)ei)[e];
        dst = ((const int*)ei)[NE + e];
    }
}

// ---- 0b) zero degree array ----
__global__ void k_zero_deg() {
    int i = blockIdx.x * blockDim.x + threadIdx.x;
    if (i < NN) g_deg[i] = 0;
}

// ---- 1) init: g_h[0] = fp16(cat(user, item)) ----
__global__ void k_init_emb(const float4* __restrict__ u4,
                           const float4* __restrict__ i4) {
    const int n4 = NN * D4;
    const int u_n4 = NU * D4;
    for (int i = blockIdx.x * blockDim.x + threadIdx.x; i < n4;
         i += gridDim.x * blockDim.x) {
        float4 v = (i < u_n4) ? u4[i] : i4[i - u_n4];
        __half2 a = __floats2half2_rn(v.x, v.y);
        __half2 b = __floats2half2_rn(v.z, v.w);
        uint2 o;
        o.x = *reinterpret_cast<unsigned*>(&a);
        o.y = *reinterpret_cast<unsigned*>(&b);
        g_h[0][i] = o;
    }
}

// ---- 2) degree histogram over dst ----
__global__ void k_hist(const void* __restrict__ ei) {
    const int is64 = g_is64;
    for (int e = blockIdx.x * blockDim.x + threadIdx.x; e < NE;
         e += gridDim.x * blockDim.x) {
        int src, dst;
        load_edge(ei, is64, e, src, dst);
        if ((unsigned)dst < NN) atomicAdd(&g_deg[dst], 1);
    }
}

// ---- 3a) block-local exclusive scan of deg -> g_off, block sums -> g_part ----
__global__ void k_scan1() {
    __shared__ int sh[SCAN_B];
    int gid = blockIdx.x * SCAN_B + threadIdx.x;
    int v = (gid < NN) ? g_deg[gid] : 0;
    sh[threadIdx.x] = v;
    __syncthreads();
    for (int d = 1; d < SCAN_B; d <<= 1) {
        int t = (threadIdx.x >= d) ? sh[threadIdx.x - d] : 0;
        __syncthreads();
        sh[threadIdx.x] += t;
        __syncthreads();
    }
    int incl = sh[threadIdx.x];
    if (gid < NN) g_off[gid] = incl - v;          // exclusive
    if (threadIdx.x == SCAN_B - 1) g_part[blockIdx.x] = incl;
}

// ---- 3b) single-block exclusive scan of block sums ----
__global__ void k_scan2() {
    __shared__ int sh[256];
    int tid = threadIdx.x;
    int v = (tid < SCAN_NB) ? g_part[tid] : 0;
    sh[tid] = v;
    __syncthreads();
    for (int d = 1; d < 256; d <<= 1) {
        int t = (tid >= d) ? sh[tid - d] : 0;
        __syncthreads();
        sh[tid] += t;
        __syncthreads();
    }
    if (tid < SCAN_NB) g_part[tid] = sh[tid] - v; // exclusive
}

// ---- 3c) add block offsets, init cursor, compute inv_deg ----
__global__ void k_scan3() {
    int gid = blockIdx.x * SCAN_B + threadIdx.x;
    if (gid < NN) {
        int o = g_off[gid] + g_part[blockIdx.x];
        g_off[gid] = o;
        g_cur[gid] = o;
        int d = g_deg[gid];
        g_inv[gid] = (d > 0) ? (1.0f / (float)d) : 0.0f;
    }
    if (gid == 0) g_off[NN] = NE;
}

// ---- 4) scatter src indices into CSR slots ----
__global__ void k_scatter(const void* __restrict__ ei) {
    const int is64 = g_is64;
    for (int e = blockIdx.x * blockDim.x + threadIdx.x; e < NE;
         e += gridDim.x * blockDim.x) {
        int src, dst;
        load_edge(ei, is64, e, src, dst);
        if ((unsigned)dst < NN && (unsigned)src < NN) {
            int pos = atomicAdd(&g_cur[dst], 1);
            g_csr[pos] = src;
        }
    }
}

// ---- helper: accumulate one fp16 row chunk (4 halves) into fp32 sums ----
__device__ __forceinline__ void acc4(uint2 v, float& sx, float& sy,
                                     float& sz, float& sw) {
    __half2 a = *reinterpret_cast<__half2*>(&v.x);
    __half2 b = *reinterpret_cast<__half2*>(&v.y);
    float2 fa = __half22float2(a);
    float2 fb = __half22float2(b);
    sx += fa.x; sy += fa.y; sz += fb.x; sw += fb.y;
}

// ---- 5) one propagation layer: a_out[n] = inv[n] * sum_{s in N(n)} a_in[s]
//         (fp16 in / fp16 out, fp32 accumulate). Warp per node, lane = 4 dims. ----
__global__ void k_layer(int in_idx) {
    const uint2* __restrict__ in = g_h[in_idx];
    uint2* __restrict__ out      = g_h[in_idx + 1];

    int warp = (blockIdx.x * blockDim.x + threadIdx.x) >> 5;
    if (warp >= NN) return;
    int lane = threadIdx.x & 31;

    int beg = g_off[warp];
    int end = g_off[warp + 1];

    float sx = 0.f, sy = 0.f, sz = 0.f, sw = 0.f;
    int e = beg;
    for (; e + 3 < end; e += 4) {
        int s0 = g_csr[e];
        int s1 = g_csr[e + 1];
        int s2 = g_csr[e + 2];
        int s3 = g_csr[e + 3];
        uint2 v0 = in[(size_t)s0 * 32 + lane];
        uint2 v1 = in[(size_t)s1 * 32 + lane];
        uint2 v2 = in[(size_t)s2 * 32 + lane];
        uint2 v3 = in[(size_t)s3 * 32 + lane];
        acc4(v0, sx, sy, sz, sw);
        acc4(v1, sx, sy, sz, sw);
        acc4(v2, sx, sy, sz, sw);
        acc4(v3, sx, sy, sz, sw);
    }
    for (; e < end; ++e) {
        int s = g_csr[e];
        uint2 v = in[(size_t)s * 32 + lane];
        acc4(v, sx, sy, sz, sw);
    }

    float idg = g_inv[warp];
    __half2 ha = __floats2half2_rn(sx * idg, sy * idg);
    __half2 hb = __floats2half2_rn(sz * idg, sw * idg);
    uint2 o;
    o.x = *reinterpret_cast<unsigned*>(&ha);
    o.y = *reinterpret_cast<unsigned*>(&hb);
    out[(size_t)warp * 32 + lane] = o;
}

// ---- 6) final combine: out = (x_fp32 + a1 + a2 + a3) / 4 ----
__global__ void k_combine(const float4* __restrict__ u4,
                          const float4* __restrict__ i4,
                          float4* __restrict__ out4) {
    const int n4 = NN * D4;
    const int u_n4 = NU * D4;
    for (int i = blockIdx.x * blockDim.x + threadIdx.x; i < n4;
         i += gridDim.x * blockDim.x) {
        float4 x = (i < u_n4) ? u4[i] : i4[i - u_n4];
        float sx = x.x, sy = x.y, sz = x.z, sw = x.w;
        acc4(g_h[1][i], sx, sy, sz, sw);
        acc4(g_h[2][i], sx, sy, sz, sw);
        acc4(g_h[3][i], sx, sy, sz, sw);
        float4 r;
        r.x = sx * 0.25f; r.y = sy * 0.25f; r.z = sz * 0.25f; r.w = sw * 0.25f;
        out4[i] = r;
    }
}

extern "C" void kernel_launch(void* const* d_in, const int* in_sizes, int n_in,
                              void* d_out, int out_size) {
    const float4* u4  = (const float4*)d_in[0];
    const float4* i4  = (const float4*)d_in[1];
    const void*   ei  = d_in[2];
    float4*       out = (float4*)d_out;

    // dtype detection + CSR build
    k_detect<<<1, 256>>>((const int*)ei);
    k_zero_deg<<<(NN + 255) / 256, 256>>>();
    k_init_emb<<<2048, 256>>>(u4, i4);
    k_hist<<<2048, 256>>>(ei);
    k_scan1<<<SCAN_NB, SCAN_B>>>();
    k_scan2<<<1, 256>>>();
    k_scan3<<<SCAN_NB, SCAN_B>>>();
    k_scatter<<<2048, 256>>>(ei);

    // 3 propagation layers (warp per node), fp16 buffers 0->1->2->3
    const int layer_blocks = (NN * 32 + 255) / 256;
    k_layer<<<layer_blocks, 256>>>(0);
    k_layer<<<layer_blocks, 256>>>(1);
    k_layer<<<layer_blocks, 256>>>(2);

    k_combine<<<2048, 256>>>(u4, i4, out);
}

// round 4
// speedup vs baseline: 1.6027x; 1.1316x over previous
#include <cuda_runtime.h>
#include <cuda_fp16.h>

#define NU 100000
#define NI 50000
#define NN 150000            // NU + NI
#define NE 3000000
#define DIM 128
#define D4  32               // DIM / 4 (float4 / uint2 chunks per row)

#define SCAN_B 1024
#define SCAN_NB 147          // ceil(NN / 1024)

// ---- device scratch (allocation-free requirement) ----
// fp16 embedding buffers: [0]=x, [1]=a1, [2]=a2. (a3 is fused into output.)
__device__ uint2 g_h[3][(size_t)NN * D4];
__device__ int    g_deg[NN];
__device__ float  g_inv[NN];
__device__ int    g_off[NN + 1];
__device__ int    g_cur[NN];
__device__ int    g_csr[NE];
__device__ int    g_part[SCAN_NB];
__device__ int    g_is64;

__device__ __forceinline__ __half2 u2h(unsigned u) {
    return *reinterpret_cast<__half2*>(&u);
}

// ---- 0a) detect edge_index element width: int64 stores high word = 0 ----
__global__ void k_detect(const int* __restrict__ ei32) {
    __shared__ int s_or[256];
    int acc = 0;
    for (int i = threadIdx.x; i < 4096; i += 256) acc |= ei32[2 * i + 1];
    s_or[threadIdx.x] = acc;
    __syncthreads();
    for (int d = 128; d > 0; d >>= 1) {
        if (threadIdx.x < d) s_or[threadIdx.x] |= s_or[threadIdx.x + d];
        __syncthreads();
    }
    if (threadIdx.x == 0) g_is64 = (s_or[0] == 0) ? 1 : 0;
}

__device__ __forceinline__ void load_edge(const void* ei, int is64, int e,
                                          int& src, int& dst) {
    if (is64) {
        src = (int)((const long long*)ei)[e];
        dst = (int)((const long long*)ei)[NE + e];
    } else {
        src = ((const int*)ei)[e];
        dst = ((const int*)ei)[NE + e];
    }
}

// ---- 0b) zero degree array ----
__global__ void k_zero_deg() {
    int i = blockIdx.x * blockDim.x + threadIdx.x;
    if (i < NN) g_deg[i] = 0;
}

// ---- 1) init: g_h[0] = fp16(cat(user, item)) ----
__global__ void k_init_emb(const float4* __restrict__ u4,
                           const float4* __restrict__ i4) {
    const int n4 = NN * D4;
    const int u_n4 = NU * D4;
    for (int i = blockIdx.x * blockDim.x + threadIdx.x; i < n4;
         i += gridDim.x * blockDim.x) {
        float4 v = (i < u_n4) ? u4[i] : i4[i - u_n4];
        __half2 a = __floats2half2_rn(v.x, v.y);
        __half2 b = __floats2half2_rn(v.z, v.w);
        uint2 o;
        o.x = *reinterpret_cast<unsigned*>(&a);
        o.y = *reinterpret_cast<unsigned*>(&b);
        g_h[0][i] = o;
    }
}

// ---- 2) degree histogram over dst ----
__global__ void k_hist(const void* __restrict__ ei) {
    const int is64 = g_is64;
    for (int e = blockIdx.x * blockDim.x + threadIdx.x; e < NE;
         e += gridDim.x * blockDim.x) {
        int src, dst;
        load_edge(ei, is64, e, src, dst);
        if ((unsigned)dst < NN) atomicAdd(&g_deg[dst], 1);
    }
}

// ---- 3a) block-local exclusive scan of deg -> g_off, block sums -> g_part ----
__global__ void k_scan1() {
    __shared__ int sh[SCAN_B];
    int gid = blockIdx.x * SCAN_B + threadIdx.x;
    int v = (gid < NN) ? g_deg[gid] : 0;
    sh[threadIdx.x] = v;
    __syncthreads();
    for (int d = 1; d < SCAN_B; d <<= 1) {
        int t = (threadIdx.x >= d) ? sh[threadIdx.x - d] : 0;
        __syncthreads();
        sh[threadIdx.x] += t;
        __syncthreads();
    }
    int incl = sh[threadIdx.x];
    if (gid < NN) g_off[gid] = incl - v;          // exclusive
    if (threadIdx.x == SCAN_B - 1) g_part[blockIdx.x] = incl;
}

// ---- 3b) single-block exclusive scan of block sums ----
__global__ void k_scan2() {
    __shared__ int sh[256];
    int tid = threadIdx.x;
    int v = (tid < SCAN_NB) ? g_part[tid] : 0;
    sh[tid] = v;
    __syncthreads();
    for (int d = 1; d < 256; d <<= 1) {
        int t = (tid >= d) ? sh[tid - d] : 0;
        __syncthreads();
        sh[tid] += t;
        __syncthreads();
    }
    if (tid < SCAN_NB) g_part[tid] = sh[tid] - v; // exclusive
}

// ---- 3c) add block offsets, init cursor, compute inv_deg ----
__global__ void k_scan3() {
    int gid = blockIdx.x * SCAN_B + threadIdx.x;
    if (gid < NN) {
        int o = g_off[gid] + g_part[blockIdx.x];
        g_off[gid] = o;
        g_cur[gid] = o;
        int d = g_deg[gid];
        g_inv[gid] = (d > 0) ? (1.0f / (float)d) : 0.0f;
    }
    if (gid == 0) g_off[NN] = NE;
}

// ---- 4) scatter src indices into CSR slots ----
__global__ void k_scatter(const void* __restrict__ ei) {
    const int is64 = g_is64;
    for (int e = blockIdx.x * blockDim.x + threadIdx.x; e < NE;
         e += gridDim.x * blockDim.x) {
        int src, dst;
        load_edge(ei, is64, e, src, dst);
        if ((unsigned)dst < NN && (unsigned)src < NN) {
            int pos = atomicAdd(&g_cur[dst], 1);
            g_csr[pos] = src;
        }
    }
}

// ---- helper: accumulate one fp16 chunk (4 halves) into fp32 sums ----
__device__ __forceinline__ void acc4(uint2 v, float& sx, float& sy,
                                     float& sz, float& sw) {
    float2 fa = __half22float2(u2h(v.x));
    float2 fb = __half22float2(u2h(v.y));
    sx += fa.x; sy += fa.y; sz += fb.x; sw += fb.y;
}

// ---- 5) propagation layer. FUSE=1: layer 3 + final combine fused.
//         Warp per node, lane handles 4 dims. Depth-2 HADD2 tree per 4 edges. ----
template<int FUSE>
__global__ void k_layer_t(int in_idx,
                          const float4* __restrict__ u4,
                          const float4* __restrict__ i4,
                          float4* __restrict__ out4) {
    const uint2* __restrict__ in = g_h[in_idx];

    int warp = (blockIdx.x * blockDim.x + threadIdx.x) >> 5;
    if (warp >= NN) return;
    int lane = threadIdx.x & 31;

    int beg = g_off[warp];
    int end = g_off[warp + 1];

    float sx = 0.f, sy = 0.f, sz = 0.f, sw = 0.f;
    int e = beg;
    for (; e + 3 < end; e += 4) {
        int s0 = g_csr[e];
        int s1 = g_csr[e + 1];
        int s2 = g_csr[e + 2];
        int s3 = g_csr[e + 3];
        uint2 v0 = in[(size_t)s0 * D4 + lane];
        uint2 v1 = in[(size_t)s1 * D4 + lane];
        uint2 v2 = in[(size_t)s2 * D4 + lane];
        uint2 v3 = in[(size_t)s3 * D4 + lane];
        // depth-2 fp16 tree, one fp32 accumulate per 4 edges
        __half2 a = __hadd2(__hadd2(u2h(v0.x), u2h(v1.x)),
                            __hadd2(u2h(v2.x), u2h(v3.x)));
        __half2 b = __hadd2(__hadd2(u2h(v0.y), u2h(v1.y)),
                            __hadd2(u2h(v2.y), u2h(v3.y)));
        float2 fa = __half22float2(a);
        float2 fb = __half22float2(b);
        sx += fa.x; sy += fa.y; sz += fb.x; sw += fb.y;
    }
    for (; e < end; ++e) {                      // tail: exact fp32 adds
        int s = g_csr[e];
        acc4(in[(size_t)s * D4 + lane], sx, sy, sz, sw);
    }

    float idg = g_inv[warp];
    float rx = sx * idg, ry = sy * idg, rz = sz * idg, rw = sw * idg;

    size_t oi = (size_t)warp * D4 + lane;
    if (FUSE) {
        // out = (x + a1 + a2 + a3) / 4 ; a2 row == in[oi], a3 == r (registers)
        float4 x = (warp < NU) ? u4[oi] : i4[oi - (size_t)NU * D4];
        float tx = x.x + rx, ty = x.y + ry, tz = x.z + rz, tw = x.w + rw;
        acc4(g_h[1][oi], tx, ty, tz, tw);
        acc4(in[oi],     tx, ty, tz, tw);
        float4 r;
        r.x = tx * 0.25f; r.y = ty * 0.25f; r.z = tz * 0.25f; r.w = tw * 0.25f;
        out4[oi] = r;
    } else {
        __half2 ha = __floats2half2_rn(rx, ry);
        __half2 hb = __floats2half2_rn(rz, rw);
        uint2 o;
        o.x = *reinterpret_cast<unsigned*>(&ha);
        o.y = *reinterpret_cast<unsigned*>(&hb);
        g_h[in_idx + 1][oi] = o;
    }
}

extern "C" void kernel_launch(void* const* d_in, const int* in_sizes, int n_in,
                              void* d_out, int out_size) {
    const float4* u4  = (const float4*)d_in[0];
    const float4* i4  = (const float4*)d_in[1];
    const void*   ei  = d_in[2];
    float4*       out = (float4*)d_out;

    // dtype detection + CSR build
    k_detect<<<1, 256>>>((const int*)ei);
    k_zero_deg<<<(NN + 255) / 256, 256>>>();
    k_init_emb<<<2048, 256>>>(u4, i4);
    k_hist<<<2048, 256>>>(ei);
    k_scan1<<<SCAN_NB, SCAN_B>>>();
    k_scan2<<<1, 256>>>();
    k_scan3<<<SCAN_NB, SCAN_B>>>();
    k_scatter<<<2048, 256>>>(ei);

    // 3 propagation layers (warp per node); layer 3 fused with final combine
    const int layer_blocks = (NN * 32 + 255) / 256;
    k_layer_t<0><<<layer_blocks, 256>>>(0, u4, i4, out);  // x  -> a1
    k_layer_t<0><<<layer_blocks, 256>>>(1, u4, i4, out);  // a1 -> a2
    k_layer_t<1><<<layer_blocks, 256>>>(2, u4, i4, out);  // a2 -> out (fused)
}